// round 1
// baseline (speedup 1.0000x reference)
#include <cuda_runtime.h>
#include <math.h>
#include <float.h>

#define NPTS   32768
#define NE     1024
#define ED     64
#define ZELEMS 2097152

// Output layout: [loss(1), z_q_st(2097152), perplexity(1), min_encodings(33554432), idx(32768)]
#define OFF_LOSS 0
#define OFF_ZQ   1
#define OFF_PERP 2097153
#define OFF_MENC 2097154
#define OFF_IDX  35651586

__device__ float g_see[NE];
__device__ float g_szz[NPTS];
__device__ int   g_idx[NPTS];
__device__ int   g_cs[NE];
__device__ float g_sum[NE * ED];
__device__ float g_new_emb[NE * ED];
__device__ float g_loss_sum;

// ---------------------------------------------------------------------------
// K1: per-code ||e||^2, per-point ||z||^2, zero accumulators
// ---------------------------------------------------------------------------
__global__ void k_prep(const float* __restrict__ z, const float* __restrict__ emb)
{
    int t = blockIdx.x * 256 + threadIdx.x;   // 32768 threads
    if (t < NE) {
        const float* e = emb + (size_t)t * ED;
        float s = 0.f;
        #pragma unroll
        for (int c = 0; c < ED; c++) { float v = e[c]; s = __fadd_rn(s, __fmul_rn(v, v)); }
        g_see[t] = s;
        g_cs[t]  = 0;
    }
    if (t == 0) g_loss_sum = 0.f;
    if (t < NPTS) {
        int b = t >> 10, hw = t & 1023;
        const float* zp = z + (size_t)b * 65536 + hw;
        float s = 0.f;
        #pragma unroll
        for (int c = 0; c < ED; c++) { float v = zp[(size_t)c << 10]; s = __fadd_rn(s, __fmul_rn(v, v)); }
        g_szz[t] = s;
    }
    g_sum[t]          = 0.f;
    g_sum[t + 32768]  = 0.f;
}

// ---------------------------------------------------------------------------
// K2: argmin over 1024 codes, tiled 64 pts x 128 codes, 4x8 per thread.
// d = (||z||^2 + ||e||^2) - 2*(z.e)  computed with the reference's op order.
// ---------------------------------------------------------------------------
__global__ __launch_bounds__(256) void k_argmin(const float* __restrict__ z,
                                                const float* __restrict__ emb,
                                                float* __restrict__ out, int out_size)
{
    __shared__ float zs[64][64];    // [k][pt]
    __shared__ float es[64][128];   // [k][code ^ (k>>2)]  (XOR swizzle)

    const int tx = threadIdx.x & 15;    // code lane
    const int ty = threadIdx.x >> 4;    // point lane (4 pts)
    const int pbase = blockIdx.x * 64;

    // load z tile (coalesced: consecutive p -> consecutive hw)
    for (int i = threadIdx.x; i < 64 * 64; i += 256) {
        int p = i & 63, k = i >> 6;
        int pn = pbase + p;
        int b = pn >> 10, hw = pn & 1023;
        zs[k][p] = z[(size_t)b * 65536 + (size_t)k * 1024 + hw];
    }

    float szz_r[4];
    #pragma unroll
    for (int q = 0; q < 4; q++) szz_r[q] = g_szz[pbase + ty * 4 + q];

    float best[4]; int bestj[4];
    #pragma unroll
    for (int q = 0; q < 4; q++) { best[q] = FLT_MAX; bestj[q] = 0; }

    for (int jc = 0; jc < NE; jc += 128) {
        __syncthreads();
        // load 128-code chunk, transposed with XOR swizzle (conflict-light both ways)
        for (int f = threadIdx.x; f < 128 * 16; f += 256) {
            int code = f >> 4;
            int s    = f & 15;
            int k4   = s << 2;
            float4 v = *(const float4*)(emb + (size_t)(jc + code) * ED + k4);
            int cc   = code ^ s;
            es[k4 + 0][cc] = v.x; es[k4 + 1][cc] = v.y;
            es[k4 + 2][cc] = v.z; es[k4 + 3][cc] = v.w;
        }
        __syncthreads();

        float acc[4][8];
        #pragma unroll
        for (int q = 0; q < 4; q++)
            #pragma unroll
            for (int c = 0; c < 8; c++) acc[q][c] = 0.f;

        #pragma unroll 4
        for (int k = 0; k < 64; k++) {
            float4 zv = *(const float4*)&zs[k][ty << 2];
            const float* ep = &es[k][tx ^ (k >> 2)];
            float ev[8];
            #pragma unroll
            for (int c = 0; c < 8; c++) ev[c] = ep[c << 4];
            float zq[4] = { zv.x, zv.y, zv.z, zv.w };
            #pragma unroll
            for (int q = 0; q < 4; q++)
                #pragma unroll
                for (int c = 0; c < 8; c++)
                    acc[q][c] = fmaf(zq[q], ev[c], acc[q][c]);
        }

        // epilogue: ascending j within thread -> first-min (jax argmin) semantics
        #pragma unroll
        for (int c = 0; c < 8; c++) {
            int j = jc + tx + (c << 4);
            float se = g_see[j];
            #pragma unroll
            for (int q = 0; q < 4; q++) {
                float d = __fsub_rn(__fadd_rn(szz_r[q], se), __fmul_rn(2.0f, acc[q][c]));
                if (d < best[q]) { best[q] = d; bestj[q] = j; }
            }
        }
    }

    // cross-thread reduction (reuse es as scratch), tie -> smaller j
    __syncthreads();
    float* rdd = &es[0][0];
    int*   rdj = (int*)(&es[0][0]) + 1024;
    #pragma unroll
    for (int q = 0; q < 4; q++) {
        int p = ty * 4 + q;
        rdd[p * 16 + tx] = best[q];
        rdj[p * 16 + tx] = bestj[q];
    }
    __syncthreads();
    if (threadIdx.x < 64) {
        int p = threadIdx.x;
        float bd = rdd[p * 16]; int bj = rdj[p * 16];
        #pragma unroll
        for (int t = 1; t < 16; t++) {
            float d = rdd[p * 16 + t]; int j = rdj[p * 16 + t];
            if (d < bd || (d == bd && j < bj)) { bd = d; bj = j; }
        }
        int n = pbase + p;
        g_idx[n] = bj;
        if (OFF_IDX + n < out_size) out[OFF_IDX + n] = (float)bj;
    }
}

// ---------------------------------------------------------------------------
// K3: cluster counts + per-cluster feature sums (scatter-add)
// ---------------------------------------------------------------------------
__global__ void k_stats(const float* __restrict__ z)
{
    int n = blockIdx.x * 256 + threadIdx.x;
    if (n >= NPTS) return;
    int j = g_idx[n];
    atomicAdd(&g_cs[j], 1);
    int b = n >> 10, hw = n & 1023;
    const float* zp = z + (size_t)b * 65536 + hw;
    float* sp = g_sum + (size_t)j * ED;
    #pragma unroll
    for (int c = 0; c < ED; c++) atomicAdd(&sp[c], zp[(size_t)c << 10]);
}

// ---------------------------------------------------------------------------
// K4: EMA update, codebook normalize, perplexity  (1 block x 1024 threads)
// ---------------------------------------------------------------------------
__global__ __launch_bounds__(1024) void k_ema(const float* __restrict__ ema_cs,
                                              const float* __restrict__ ema_w,
                                              float* __restrict__ out, int out_size)
{
    __shared__ float red[1024];
    int j = threadIdx.x;
    const float DEC = 0.99f;
    const float OMD = (float)(1.0 - 0.99);

    float cs  = (float)g_cs[j];
    float ncs = __fadd_rn(__fmul_rn(DEC, ema_cs[j]), __fmul_rn(OMD, cs));

    red[j] = ncs; __syncthreads();
    for (int s = 512; s > 0; s >>= 1) { if (j < s) red[j] = __fadd_rn(red[j], red[j + s]); __syncthreads(); }
    float n = red[0];
    __syncthreads();

    // perplexity = exp(-sum p*log(p+1e-10)),  p = cs/32768 (exact: /2^15)
    float p    = cs * (1.0f / 32768.0f);
    float term = __fmul_rn(p, logf(__fadd_rn(p, 1e-10f)));
    red[j] = term; __syncthreads();
    for (int s = 512; s > 0; s >>= 1) { if (j < s) red[j] = __fadd_rn(red[j], red[j + s]); __syncthreads(); }
    if (j == 0 && OFF_PERP < out_size) out[OFF_PERP] = expf(-red[0]);

    float denom = __fadd_rn(n, (float)(1024 * 1e-5));
    float csn   = __fmul_rn(__fdiv_rn(__fadd_rn(ncs, 1e-5f), denom), n);
    #pragma unroll
    for (int c = 0; c < ED; c++) {
        float nw = __fadd_rn(__fmul_rn(DEC, ema_w[j * ED + c]),
                             __fmul_rn(OMD, g_sum[j * ED + c]));
        g_new_emb[j * ED + c] = __fdiv_rn(nw, csn);
    }
}

// ---------------------------------------------------------------------------
// K5: z_q_st = z + (z_q - z), accumulate loss sum
// ---------------------------------------------------------------------------
__global__ void k_zq(const float* __restrict__ z, float* __restrict__ out, int out_size)
{
    __shared__ float red[256];
    int m = blockIdx.x * 256 + threadIdx.x;
    float sq = 0.f;
    if (m < ZELEMS && OFF_ZQ + m < out_size) {
        int b = m >> 16; int rem = m & 65535;
        int c = rem >> 10; int hw = rem & 1023;
        int n = (b << 10) | hw;
        float zv = z[m];
        float e  = g_new_emb[(size_t)g_idx[n] * ED + c];
        float diff = __fsub_rn(e, zv);
        out[OFF_ZQ + m] = __fadd_rn(zv, diff);
        sq = __fmul_rn(diff, diff);
    }
    red[threadIdx.x] = sq; __syncthreads();
    for (int s = 128; s > 0; s >>= 1) { if (threadIdx.x < s) red[threadIdx.x] += red[threadIdx.x + s]; __syncthreads(); }
    if (threadIdx.x == 0) atomicAdd(&g_loss_sum, red[0]);
}

// ---------------------------------------------------------------------------
// K6: one-hot min_encodings (one block per row; float2 stores - base offset is
// only 8B-aligned)
// ---------------------------------------------------------------------------
__global__ void k_menc(float* __restrict__ out, int out_size)
{
    int n = blockIdx.x;
    int j = g_idx[n];
    size_t base = (size_t)OFF_MENC + (size_t)n * NE;
    if (base + NE > (size_t)out_size) return;
    int t = threadIdx.x;            // 256 threads, 512 float2 per row
    #pragma unroll
    for (int h = 0; h < 512; h += 256) {
        int f2 = t + h;
        float2 v = make_float2(0.f, 0.f);
        if ((j >> 1) == f2) { if (j & 1) v.y = 1.0f; else v.x = 1.0f; }
        *(float2*)(out + base + (size_t)f2 * 2) = v;
    }
}

// ---------------------------------------------------------------------------
// K7: loss = BETA * mean((z_q - z)^2)
// ---------------------------------------------------------------------------
__global__ void k_loss(float* __restrict__ out, int out_size)
{
    if (OFF_LOSS < out_size)
        out[OFF_LOSS] = __fmul_rn(0.25f, __fdiv_rn(g_loss_sum, 2097152.0f));
}

// ---------------------------------------------------------------------------
extern "C" void kernel_launch(void* const* d_in, const int* in_sizes, int n_in,
                              void* d_out, int out_size)
{
    // Robust input binding by element count: z=2097152, ema_cluster_size=1024,
    // emb_w = first 65536-sized, ema_w = second 65536-sized.
    const float* z = 0; const float* emb = 0; const float* ecs = 0; const float* ew = 0;
    for (int i = 0; i < n_in; i++) {
        if (in_sizes[i] == ZELEMS)      z   = (const float*)d_in[i];
        else if (in_sizes[i] == NE)     ecs = (const float*)d_in[i];
        else if (in_sizes[i] == NE * ED) { if (!emb) emb = (const float*)d_in[i]; else ew = (const float*)d_in[i]; }
    }
    if (!z || !emb || !ecs || !ew) { // fall back to declared order
        z = (const float*)d_in[0]; emb = (const float*)d_in[1];
        ecs = (const float*)d_in[2]; ew = (const float*)d_in[3];
    }
    float* out = (float*)d_out;

    k_prep  <<<128, 256>>>(z, emb);
    k_argmin<<<512, 256>>>(z, emb, out, out_size);
    k_stats <<<128, 256>>>(z);
    k_ema   <<<1, 1024>>>(ecs, ew, out, out_size);
    k_zq    <<<8192, 256>>>(z, out, out_size);
    k_menc  <<<NPTS, 256>>>(out, out_size);
    k_loss  <<<1, 1>>>(out, out_size);
}

// round 2
// speedup vs baseline: 1.6305x; 1.6305x over previous
#include <cuda_runtime.h>
#include <math.h>
#include <float.h>

#define NPTS   32768
#define NE     1024
#define ED     64
#define ZELEMS 2097152

// Output layout: [loss(1), z_q_st(2097152), perplexity(1), min_encodings(33554432), idx(32768)]
#define OFF_LOSS 0
#define OFF_ZQ   1
#define OFF_PERP 2097153
#define OFF_MENC 2097154
#define OFF_IDX  35651586

__device__ float g_see[NE];
__device__ float g_szz[NPTS];
__device__ int   g_idx[NPTS];
__device__ int   g_cs[NE];
__device__ float g_sum[NE * ED];
__device__ float g_new_emb[NE * ED];
__device__ float g_inv_csn[NE];
__device__ float g_loss_sum;

// ---------------------------------------------------------------------------
// K1: per-code ||e||^2, per-point ||z||^2, zero accumulators
// ---------------------------------------------------------------------------
__global__ void k_prep(const float* __restrict__ z, const float* __restrict__ emb)
{
    int t = blockIdx.x * 256 + threadIdx.x;   // 32768 threads
    if (t < NE) {
        const float* e = emb + (size_t)t * ED;
        float s = 0.f;
        #pragma unroll
        for (int c = 0; c < ED; c++) { float v = e[c]; s = __fadd_rn(s, __fmul_rn(v, v)); }
        g_see[t] = s;
        g_cs[t]  = 0;
    }
    if (t == 0) g_loss_sum = 0.f;
    if (t < NPTS) {
        int b = t >> 10, hw = t & 1023;
        const float* zp = z + (size_t)b * 65536 + hw;
        float s = 0.f;
        #pragma unroll
        for (int c = 0; c < ED; c++) { float v = zp[(size_t)c << 10]; s = __fadd_rn(s, __fmul_rn(v, v)); }
        g_szz[t] = s;
    }
    g_sum[t]          = 0.f;
    g_sum[t + 32768]  = 0.f;
}

// ---------------------------------------------------------------------------
// K2: argmin over 1024 codes, tiled 64 pts x 128 codes, 4x8 per thread.
// d = (||z||^2 + ||e||^2) - 2*(z.e)  computed with the reference's op order.
// ---------------------------------------------------------------------------
__global__ __launch_bounds__(256) void k_argmin(const float* __restrict__ z,
                                                const float* __restrict__ emb,
                                                float* __restrict__ out, int out_size)
{
    __shared__ float zs[64][64];    // [k][pt]
    __shared__ float es[64][128];   // [k][code ^ (k>>2)]  (XOR swizzle)

    const int tx = threadIdx.x & 15;    // code lane
    const int ty = threadIdx.x >> 4;    // point lane (4 pts)
    const int pbase = blockIdx.x * 64;

    // load z tile (coalesced: consecutive p -> consecutive hw)
    for (int i = threadIdx.x; i < 64 * 64; i += 256) {
        int p = i & 63, k = i >> 6;
        int pn = pbase + p;
        int b = pn >> 10, hw = pn & 1023;
        zs[k][p] = z[(size_t)b * 65536 + (size_t)k * 1024 + hw];
    }

    float szz_r[4];
    #pragma unroll
    for (int q = 0; q < 4; q++) szz_r[q] = g_szz[pbase + ty * 4 + q];

    float best[4]; int bestj[4];
    #pragma unroll
    for (int q = 0; q < 4; q++) { best[q] = FLT_MAX; bestj[q] = 0; }

    for (int jc = 0; jc < NE; jc += 128) {
        __syncthreads();
        // load 128-code chunk, transposed with XOR swizzle (conflict-light both ways)
        for (int f = threadIdx.x; f < 128 * 16; f += 256) {
            int code = f >> 4;
            int s    = f & 15;
            int k4   = s << 2;
            float4 v = *(const float4*)(emb + (size_t)(jc + code) * ED + k4);
            int cc   = code ^ s;
            es[k4 + 0][cc] = v.x; es[k4 + 1][cc] = v.y;
            es[k4 + 2][cc] = v.z; es[k4 + 3][cc] = v.w;
        }
        __syncthreads();

        float acc[4][8];
        #pragma unroll
        for (int q = 0; q < 4; q++)
            #pragma unroll
            for (int c = 0; c < 8; c++) acc[q][c] = 0.f;

        #pragma unroll 4
        for (int k = 0; k < 64; k++) {
            float4 zv = *(const float4*)&zs[k][ty << 2];
            const float* ep = &es[k][tx ^ (k >> 2)];
            float ev[8];
            #pragma unroll
            for (int c = 0; c < 8; c++) ev[c] = ep[c << 4];
            float zq[4] = { zv.x, zv.y, zv.z, zv.w };
            #pragma unroll
            for (int q = 0; q < 4; q++)
                #pragma unroll
                for (int c = 0; c < 8; c++)
                    acc[q][c] = fmaf(zq[q], ev[c], acc[q][c]);
        }

        // epilogue: ascending j within thread -> first-min (jax argmin) semantics
        #pragma unroll
        for (int c = 0; c < 8; c++) {
            int j = jc + tx + (c << 4);
            float se = g_see[j];
            #pragma unroll
            for (int q = 0; q < 4; q++) {
                float d = __fsub_rn(__fadd_rn(szz_r[q], se), __fmul_rn(2.0f, acc[q][c]));
                if (d < best[q]) { best[q] = d; bestj[q] = j; }
            }
        }
    }

    // cross-thread reduction (reuse es as scratch), tie -> smaller j
    __syncthreads();
    float* rdd = &es[0][0];
    int*   rdj = (int*)(&es[0][0]) + 1024;
    #pragma unroll
    for (int q = 0; q < 4; q++) {
        int p = ty * 4 + q;
        rdd[p * 16 + tx] = best[q];
        rdj[p * 16 + tx] = bestj[q];
    }
    __syncthreads();
    if (threadIdx.x < 64) {
        int p = threadIdx.x;
        float bd = rdd[p * 16]; int bj = rdj[p * 16];
        #pragma unroll
        for (int t = 1; t < 16; t++) {
            float d = rdd[p * 16 + t]; int j = rdj[p * 16 + t];
            if (d < bd || (d == bd && j < bj)) { bd = d; bj = j; }
        }
        int n = pbase + p;
        g_idx[n] = bj;
        if (OFF_IDX + n < out_size) out[OFF_IDX + n] = (float)bj;
    }
}

// ---------------------------------------------------------------------------
// K3: cluster counts + per-cluster feature sums (scatter-add)
// ---------------------------------------------------------------------------
__global__ void k_stats(const float* __restrict__ z)
{
    int n = blockIdx.x * 256 + threadIdx.x;
    if (n >= NPTS) return;
    int j = g_idx[n];
    atomicAdd(&g_cs[j], 1);
    int b = n >> 10, hw = n & 1023;
    const float* zp = z + (size_t)b * 65536 + hw;
    float* sp = g_sum + (size_t)j * ED;
    #pragma unroll
    for (int c = 0; c < ED; c++) atomicAdd(&sp[c], zp[(size_t)c << 10]);
}

// ---------------------------------------------------------------------------
// K4a: scalar reductions (n, perplexity) + one reciprocal per code.
// 1 block x 1024 threads, but now only ~1 division per thread.
// ---------------------------------------------------------------------------
__global__ __launch_bounds__(1024) void k_ema_reduce(const float* __restrict__ ema_cs,
                                                     float* __restrict__ out, int out_size)
{
    __shared__ float red[1024];
    int j = threadIdx.x;
    const float DEC = 0.99f;
    const float OMD = (float)(1.0 - 0.99);

    float cs  = (float)g_cs[j];
    float ncs = __fadd_rn(__fmul_rn(DEC, ema_cs[j]), __fmul_rn(OMD, cs));

    red[j] = ncs; __syncthreads();
    for (int s = 512; s > 0; s >>= 1) { if (j < s) red[j] = __fadd_rn(red[j], red[j + s]); __syncthreads(); }
    float n = red[0];
    __syncthreads();

    // perplexity = exp(-sum p*log(p+1e-10)),  p = cs/32768 (exact: /2^15)
    float p    = cs * (1.0f / 32768.0f);
    float term = __fmul_rn(p, logf(__fadd_rn(p, 1e-10f)));
    red[j] = term; __syncthreads();
    for (int s = 512; s > 0; s >>= 1) { if (j < s) red[j] = __fadd_rn(red[j], red[j + s]); __syncthreads(); }
    if (j == 0 && OFF_PERP < out_size) out[OFF_PERP] = expf(-red[0]);

    float denom = __fadd_rn(n, (float)(1024 * 1e-5));
    float csn   = __fmul_rn(__fdiv_rn(__fadd_rn(ncs, 1e-5f), denom), n);
    g_inv_csn[j] = __fdiv_rn(1.0f, csn);
}

// ---------------------------------------------------------------------------
// K4b: codebook update, fully parallel over 1024x64 elements.
// ---------------------------------------------------------------------------
__global__ void k_ema_update(const float* __restrict__ ema_w)
{
    int m = blockIdx.x * 256 + threadIdx.x;   // 65536 threads
    const float DEC = 0.99f;
    const float OMD = (float)(1.0 - 0.99);
    int j = m >> 6;
    float nw = __fadd_rn(__fmul_rn(DEC, ema_w[m]), __fmul_rn(OMD, g_sum[m]));
    g_new_emb[m] = __fmul_rn(nw, g_inv_csn[j]);
}

// ---------------------------------------------------------------------------
// K5: z_q_st = z + (z_q - z), accumulate loss sum
// ---------------------------------------------------------------------------
__global__ void k_zq(const float* __restrict__ z, float* __restrict__ out, int out_size)
{
    __shared__ float red[256];
    int m = blockIdx.x * 256 + threadIdx.x;
    float sq = 0.f;
    if (m < ZELEMS && OFF_ZQ + m < out_size) {
        int b = m >> 16; int rem = m & 65535;
        int c = rem >> 10; int hw = rem & 1023;
        int n = (b << 10) | hw;
        float zv = z[m];
        float e  = g_new_emb[(size_t)g_idx[n] * ED + c];
        float diff = __fsub_rn(e, zv);
        out[OFF_ZQ + m] = __fadd_rn(zv, diff);
        sq = __fmul_rn(diff, diff);
    }
    red[threadIdx.x] = sq; __syncthreads();
    for (int s = 128; s > 0; s >>= 1) { if (threadIdx.x < s) red[threadIdx.x] += red[threadIdx.x + s]; __syncthreads(); }
    if (threadIdx.x == 0) atomicAdd(&g_loss_sum, red[0]);
}

// ---------------------------------------------------------------------------
// K6: one-hot min_encodings (one block per row; float2 stores - base offset is
// only 8B-aligned)
// ---------------------------------------------------------------------------
__global__ void k_menc(float* __restrict__ out, int out_size)
{
    int n = blockIdx.x;
    int j = g_idx[n];
    size_t base = (size_t)OFF_MENC + (size_t)n * NE;
    if (base + NE > (size_t)out_size) return;
    int t = threadIdx.x;            // 256 threads, 512 float2 per row
    #pragma unroll
    for (int h = 0; h < 512; h += 256) {
        int f2 = t + h;
        float2 v = make_float2(0.f, 0.f);
        if ((j >> 1) == f2) { if (j & 1) v.y = 1.0f; else v.x = 1.0f; }
        *(float2*)(out + base + (size_t)f2 * 2) = v;
    }
}

// ---------------------------------------------------------------------------
// K7: loss = BETA * mean((z_q - z)^2)
// ---------------------------------------------------------------------------
__global__ void k_loss(float* __restrict__ out, int out_size)
{
    if (OFF_LOSS < out_size)
        out[OFF_LOSS] = __fmul_rn(0.25f, __fdiv_rn(g_loss_sum, 2097152.0f));
}

// ---------------------------------------------------------------------------
extern "C" void kernel_launch(void* const* d_in, const int* in_sizes, int n_in,
                              void* d_out, int out_size)
{
    // Robust input binding by element count: z=2097152, ema_cluster_size=1024,
    // emb_w = first 65536-sized, ema_w = second 65536-sized.
    const float* z = 0; const float* emb = 0; const float* ecs = 0; const float* ew = 0;
    for (int i = 0; i < n_in; i++) {
        if (in_sizes[i] == ZELEMS)      z   = (const float*)d_in[i];
        else if (in_sizes[i] == NE)     ecs = (const float*)d_in[i];
        else if (in_sizes[i] == NE * ED) { if (!emb) emb = (const float*)d_in[i]; else ew = (const float*)d_in[i]; }
    }
    if (!z || !emb || !ecs || !ew) { // fall back to declared order
        z = (const float*)d_in[0]; emb = (const float*)d_in[1];
        ecs = (const float*)d_in[2]; ew = (const float*)d_in[3];
    }
    float* out = (float*)d_out;

    k_prep      <<<128, 256>>>(z, emb);
    k_argmin    <<<512, 256>>>(z, emb, out, out_size);
    k_stats     <<<128, 256>>>(z);
    k_ema_reduce<<<1, 1024>>>(ecs, out, out_size);
    k_ema_update<<<256, 256>>>(ew);
    k_zq        <<<8192, 256>>>(z, out, out_size);
    k_menc      <<<NPTS, 256>>>(out, out_size);
    k_loss      <<<1, 1>>>(out, out_size);
}

// round 3
// speedup vs baseline: 1.9076x; 1.1699x over previous
#include <cuda_runtime.h>
#include <math.h>
#include <float.h>

#define NPTS   32768
#define NE     1024
#define ED     64
#define ZELEMS 2097152

// Output layout: [loss(1), z_q_st(2097152), perplexity(1), min_encodings(33554432), idx(32768)]
#define OFF_LOSS 0
#define OFF_ZQ   1
#define OFF_PERP 2097153
#define OFF_MENC 2097154
#define OFF_IDX  35651586

__device__ float g_see[NE];
__device__ float g_szz[NPTS];
__device__ int   g_idx[NPTS];
__device__ int   g_cs[NE];
__device__ float g_sum[NE * ED];
__device__ float g_new_emb[NE * ED];
__device__ float g_inv_csn[NE];
__device__ float g_loss_sum;

// ---------------------------------------------------------------------------
// K1: per-code ||e||^2, per-point ||z||^2, zero accumulators
// ---------------------------------------------------------------------------
__global__ void k_prep(const float* __restrict__ z, const float* __restrict__ emb)
{
    int t = blockIdx.x * 256 + threadIdx.x;   // 32768 threads
    if (t < NE) {
        const float* e = emb + (size_t)t * ED;
        float s = 0.f;
        #pragma unroll
        for (int c = 0; c < ED; c++) { float v = e[c]; s = __fadd_rn(s, __fmul_rn(v, v)); }
        g_see[t] = s;
        g_cs[t]  = 0;
    }
    if (t == 0) g_loss_sum = 0.f;
    if (t < NPTS) {
        int b = t >> 10, hw = t & 1023;
        const float* zp = z + (size_t)b * 65536 + hw;
        float s = 0.f;
        #pragma unroll
        for (int c = 0; c < ED; c++) { float v = zp[(size_t)c << 10]; s = __fadd_rn(s, __fmul_rn(v, v)); }
        g_szz[t] = s;
    }
    g_sum[t]          = 0.f;
    g_sum[t + 32768]  = 0.f;
}

// ---------------------------------------------------------------------------
// K2: argmin over 1024 codes, tiled 128 pts x 128 codes, 8x8 per thread,
// with cluster stats (counts + feature sums) fused into the epilogue.
// d = (||z||^2 + ||e||^2) - 2*(z.e)  computed with the reference's op order.
// Dynamic smem: zs[64][128] + es[64][128] = 64KB.
// ---------------------------------------------------------------------------
__global__ __launch_bounds__(256, 2) void k_argmin(const float* __restrict__ z,
                                                   const float* __restrict__ emb,
                                                   float* __restrict__ out, int out_size)
{
    extern __shared__ float dyn[];
    float (*zs)[128] = (float (*)[128])dyn;            // [k][pt]
    float (*es)[128] = (float (*)[128])(dyn + 64*128); // [k][code ^ (k>>2)]
    __shared__ int sbj[128];

    const int tx = threadIdx.x & 15;    // code lane (8 codes, stride 16)
    const int ty = threadIdx.x >> 4;    // point lane (8 pts)
    const int pbase = blockIdx.x * 128;

    // load z tile (coalesced: consecutive p -> consecutive hw)
    for (int i = threadIdx.x; i < 64 * 128; i += 256) {
        int p = i & 127, k = i >> 7;
        int pn = pbase + p;
        int b = pn >> 10, hw = pn & 1023;
        zs[k][p] = z[(size_t)b * 65536 + (size_t)k * 1024 + hw];
    }

    float szz_r[8];
    #pragma unroll
    for (int q = 0; q < 8; q++) szz_r[q] = g_szz[pbase + ty * 8 + q];

    float best[8]; int bestj[8];
    #pragma unroll
    for (int q = 0; q < 8; q++) { best[q] = FLT_MAX; bestj[q] = 0; }

    for (int jc = 0; jc < NE; jc += 128) {
        __syncthreads();
        // load 128-code chunk, transposed with XOR swizzle
        for (int f = threadIdx.x; f < 128 * 16; f += 256) {
            int code = f >> 4;
            int s    = f & 15;
            int k4   = s << 2;
            float4 v = *(const float4*)(emb + (size_t)(jc + code) * ED + k4);
            int cc   = code ^ s;
            es[k4 + 0][cc] = v.x; es[k4 + 1][cc] = v.y;
            es[k4 + 2][cc] = v.z; es[k4 + 3][cc] = v.w;
        }
        __syncthreads();

        float acc[8][8];
        #pragma unroll
        for (int q = 0; q < 8; q++)
            #pragma unroll
            for (int c = 0; c < 8; c++) acc[q][c] = 0.f;

        #pragma unroll 2
        for (int k = 0; k < 64; k++) {
            float4 za = *(const float4*)&zs[k][ty << 3];
            float4 zb = *(const float4*)&zs[k][(ty << 3) + 4];
            const float* ep = &es[k][tx ^ (k >> 2)];
            float ev[8];
            #pragma unroll
            for (int c = 0; c < 8; c++) ev[c] = ep[c << 4];
            float zq[8] = { za.x, za.y, za.z, za.w, zb.x, zb.y, zb.z, zb.w };
            #pragma unroll
            for (int q = 0; q < 8; q++)
                #pragma unroll
                for (int c = 0; c < 8; c++)
                    acc[q][c] = fmaf(zq[q], ev[c], acc[q][c]);
        }

        // epilogue: ascending j within thread -> first-min (jax argmin) semantics
        #pragma unroll
        for (int c = 0; c < 8; c++) {
            int j = jc + tx + (c << 4);
            float se = g_see[j];
            #pragma unroll
            for (int q = 0; q < 8; q++) {
                float d = __fsub_rn(__fadd_rn(szz_r[q], se), __fmul_rn(2.0f, acc[q][c]));
                if (d < best[q]) { best[q] = d; bestj[q] = j; }
            }
        }
    }

    // cross-thread reduction (reuse es as scratch), tie -> smaller j
    __syncthreads();
    float* rdd = &es[0][0];                    // 128*16 floats
    int*   rdj = (int*)&es[0][0] + 2048;       // 128*16 ints
    #pragma unroll
    for (int q = 0; q < 8; q++) {
        int p = ty * 8 + q;
        rdd[p * 16 + tx] = best[q];
        rdj[p * 16 + tx] = bestj[q];
    }
    __syncthreads();
    if (threadIdx.x < 128) {
        int p = threadIdx.x;
        float bd = rdd[p * 16]; int bj = rdj[p * 16];
        #pragma unroll
        for (int t = 1; t < 16; t++) {
            float d = rdd[p * 16 + t]; int j = rdj[p * 16 + t];
            if (d < bd || (d == bd && j < bj)) { bd = d; bj = j; }
        }
        int n = pbase + p;
        g_idx[n] = bj;
        sbj[p]   = bj;
        if (OFF_IDX + n < out_size) out[OFF_IDX + n] = (float)bj;
        atomicAdd(&g_cs[bj], 1);
    }
    __syncthreads();

    // fused cluster-sum scatter: z tile is still in zs
    {
        int p  = threadIdx.x >> 1;            // 2 threads per point
        int k0 = (threadIdx.x & 1) << 5;      // 32 dims each
        float* sp = g_sum + (size_t)sbj[p] * ED;
        #pragma unroll
        for (int kk = 0; kk < 32; kk++)
            atomicAdd(&sp[k0 + kk], zs[k0 + kk][p]);
    }
}

// ---------------------------------------------------------------------------
// K3a: scalar reductions (n, perplexity) + one reciprocal per code
// ---------------------------------------------------------------------------
__global__ __launch_bounds__(1024) void k_ema_reduce(const float* __restrict__ ema_cs,
                                                     float* __restrict__ out, int out_size)
{
    __shared__ float red[1024];
    int j = threadIdx.x;
    const float DEC = 0.99f;
    const float OMD = (float)(1.0 - 0.99);

    float cs  = (float)g_cs[j];
    float ncs = __fadd_rn(__fmul_rn(DEC, ema_cs[j]), __fmul_rn(OMD, cs));

    red[j] = ncs; __syncthreads();
    for (int s = 512; s > 0; s >>= 1) { if (j < s) red[j] = __fadd_rn(red[j], red[j + s]); __syncthreads(); }
    float n = red[0];
    __syncthreads();

    float p    = cs * (1.0f / 32768.0f);
    float term = __fmul_rn(p, logf(__fadd_rn(p, 1e-10f)));
    red[j] = term; __syncthreads();
    for (int s = 512; s > 0; s >>= 1) { if (j < s) red[j] = __fadd_rn(red[j], red[j + s]); __syncthreads(); }
    if (j == 0 && OFF_PERP < out_size) out[OFF_PERP] = expf(-red[0]);

    float denom = __fadd_rn(n, (float)(1024 * 1e-5));
    float csn   = __fmul_rn(__fdiv_rn(__fadd_rn(ncs, 1e-5f), denom), n);
    g_inv_csn[j] = __fdiv_rn(1.0f, csn);
}

// ---------------------------------------------------------------------------
// K3b: codebook update, fully parallel over 1024x64 elements
// ---------------------------------------------------------------------------
__global__ void k_ema_update(const float* __restrict__ ema_w)
{
    int m = blockIdx.x * 256 + threadIdx.x;   // 65536 threads
    const float DEC = 0.99f;
    const float OMD = (float)(1.0 - 0.99);
    int j = m >> 6;
    float nw = __fadd_rn(__fmul_rn(DEC, ema_w[m]), __fmul_rn(OMD, g_sum[m]));
    g_new_emb[m] = __fmul_rn(nw, g_inv_csn[j]);
}

// ---------------------------------------------------------------------------
// K4: z_q_st = z + (z_q - z), accumulate loss sum
// ---------------------------------------------------------------------------
__global__ void k_zq(const float* __restrict__ z, float* __restrict__ out, int out_size)
{
    __shared__ float red[256];
    int m = blockIdx.x * 256 + threadIdx.x;
    float sq = 0.f;
    if (m < ZELEMS && OFF_ZQ + m < out_size) {
        int b = m >> 16; int rem = m & 65535;
        int c = rem >> 10; int hw = rem & 1023;
        int n = (b << 10) | hw;
        float zv = z[m];
        float e  = g_new_emb[(size_t)g_idx[n] * ED + c];
        float diff = __fsub_rn(e, zv);
        out[OFF_ZQ + m] = __fadd_rn(zv, diff);
        sq = __fmul_rn(diff, diff);
    }
    red[threadIdx.x] = sq; __syncthreads();
    for (int s = 128; s > 0; s >>= 1) { if (threadIdx.x < s) red[threadIdx.x] += red[threadIdx.x + s]; __syncthreads(); }
    if (threadIdx.x == 0) atomicAdd(&g_loss_sum, red[0]);
}

// ---------------------------------------------------------------------------
// K5: one-hot min_encodings with float4 bulk stores (row base is ≡2 mod 4
// elements, so elements [2,1022) are 16B-aligned), loss folded into block 0.
// ---------------------------------------------------------------------------
__global__ void k_menc(float* __restrict__ out, int out_size)
{
    int n = blockIdx.x;
    int j = g_idx[n];
    size_t base = (size_t)OFF_MENC + (size_t)n * NE;
    if (base + NE > (size_t)out_size) return;
    float* row = out + base;
    int t = threadIdx.x;            // 128 threads

    if (t == 0) {
        *(float2*)row          = make_float2(j == 0 ? 1.f : 0.f, j == 1 ? 1.f : 0.f);
        *(float2*)(row + 1022) = make_float2(j == 1022 ? 1.f : 0.f, j == 1023 ? 1.f : 0.f);
        if (n == 0 && OFF_LOSS < out_size)
            out[OFF_LOSS] = __fmul_rn(0.25f, __fdiv_rn(g_loss_sum, 2097152.0f));
    }
    #pragma unroll
    for (int f = t; f < 255; f += 128) {
        int e0 = 2 + (f << 2);
        float4 v = make_float4(0.f, 0.f, 0.f, 0.f);
        int d = j - e0;
        if (d >= 0 && d < 4) ((float*)&v)[d] = 1.0f;
        *(float4*)(row + e0) = v;
    }
}

// ---------------------------------------------------------------------------
extern "C" void kernel_launch(void* const* d_in, const int* in_sizes, int n_in,
                              void* d_out, int out_size)
{
    const float* z = 0; const float* emb = 0; const float* ecs = 0; const float* ew = 0;
    for (int i = 0; i < n_in; i++) {
        if (in_sizes[i] == ZELEMS)      z   = (const float*)d_in[i];
        else if (in_sizes[i] == NE)     ecs = (const float*)d_in[i];
        else if (in_sizes[i] == NE * ED) { if (!emb) emb = (const float*)d_in[i]; else ew = (const float*)d_in[i]; }
    }
    if (!z || !emb || !ecs || !ew) {
        z = (const float*)d_in[0]; emb = (const float*)d_in[1];
        ecs = (const float*)d_in[2]; ew = (const float*)d_in[3];
    }
    float* out = (float*)d_out;

    static int smem_set = 0;
    if (!smem_set) {
        cudaFuncSetAttribute(k_argmin, cudaFuncAttributeMaxDynamicSharedMemorySize, 65536);
        smem_set = 1;
    }

    k_prep      <<<128, 256>>>(z, emb);
    k_argmin    <<<256, 256, 65536>>>(z, emb, out, out_size);
    k_ema_reduce<<<1, 1024>>>(ecs, out, out_size);
    k_ema_update<<<256, 256>>>(ew);
    k_zq        <<<8192, 256>>>(z, out, out_size);
    k_menc      <<<NPTS, 128>>>(out, out_size);
}